// round 6
// baseline (speedup 1.0000x reference)
#include <cuda_runtime.h>
#include <cstdint>

// Problem constants (DescrptSeA)
#define NF      2
#define NLOC    4096
#define NALL    4608
#define NROW    (NF * NLOC)
#define NNEI    138
#define SEC1    46      // type-0 neighbors: [0,46), type-1: [46,138)
#define MDIM    100
#define AXIS    16
#define NTHREADS 512
#define GRID    148

typedef unsigned long long ull;

// ---------------------------------------------------------------------------
// dtype probe: reference declares int64 indices, but JAX may emit int32.
// ---------------------------------------------------------------------------
__device__ int g_is64[2];

__global__ void probe_kernel(const unsigned* __restrict__ nlist_w,
                             const unsigned* __restrict__ atype_w) {
    if (threadIdx.x == 0 && blockIdx.x == 0) {
        int nz = 0;
        for (int p = 0; p < 512; p++) nz += (nlist_w[2 * p + 1] != 0u);
        g_is64[0] = (nz == 0) ? 1 : 0;
        nz = 0;
        for (int p = 0; p < 512; p++) nz += (atype_w[2 * p + 1] != 0u);
        g_is64[1] = (nz == 0) ? 1 : 0;
    }
}

__device__ __forceinline__ float tanh_ap(float x) {
    float y;
    asm("tanh.approx.f32 %0, %1;" : "=f"(y) : "f"(x));
    return y;
}

// ---- packed f32x2 helpers --------------------------------------------------
__device__ __forceinline__ ull pack2(float lo, float hi) {
    ull r;
    asm("mov.b64 %0, {%1, %2};" : "=l"(r) : "f"(lo), "f"(hi));
    return r;
}
__device__ __forceinline__ ull ffma2(ull a, ull b, ull c) {
    ull d;
    asm("fma.rn.f32x2 %0, %1, %2, %3;" : "=l"(d) : "l"(a), "l"(b), "l"(c));
    return d;
}
__device__ __forceinline__ ull fadd2(ull a, ull b) {
    ull d;
    asm("add.rn.f32x2 %0, %1, %2;" : "=l"(d) : "l"(a), "l"(b));
    return d;
}
__device__ __forceinline__ float hsum2(ull a) {
    float lo, hi;
    asm("mov.b64 {%0, %1}, %2;" : "=f"(lo), "=f"(hi) : "l"(a));
    return lo + hi;
}

__device__ __forceinline__ long long load_idx(const void* p, long long i, int is64) {
    if (is64) return ((const long long*)p)[i];
    return (long long)((const int*)p)[i];
}

struct SM {
    alignas(16) float env[NNEI][4];      // normalized env rows
    alignas(16) float h1[NNEI][52];      // 50 + pad (16B rows)
    alignas(16) float h0[NNEI][28];      // 25 + zero pad (16B rows)
    alignas(16) float w1T[2][50][28];    // [t][k][j], j>=25 -> 0
    alignas(16) float w0s[2][25];
    float b0s[2][25];
    alignas(16) float xyzp[5][4][MDIM];  // stage-2 partials per chunk
    alignas(16) float xyz[4][MDIM];
};

__global__ __launch_bounds__(NTHREADS, 1)
void desc_kernel(const void* __restrict__ nlist_,
                 const float* __restrict__ coord,
                 const void* __restrict__ atype_,
                 const float* __restrict__ mean,
                 const float* __restrict__ stdv,
                 const float* __restrict__ w0,
                 const float* __restrict__ b0,
                 const float* __restrict__ w1,
                 const float* __restrict__ b1,
                 const float* __restrict__ w2,
                 const float* __restrict__ b2,
                 float* __restrict__ out)
{
    extern __shared__ unsigned char smem_raw[];
    SM& sm = *reinterpret_cast<SM*>(smem_raw);

    const int tid = threadIdx.x;
    const int is64n = g_is64[0];
    const int is64a = g_is64[1];

    // ---- one-time smem staging ------------------------------------------
    for (int x = tid; x < 50; x += NTHREADS) {
        int t = x / 25, j = x % 25;
        sm.w0s[t][j] = w0[x];
        sm.b0s[t][j] = b0[x];
    }
    // w1 transposed+padded: w1T[t][k][j] = w1[t][j][k], j>=25 -> 0
    for (int x = tid; x < 2 * 50 * 28; x += NTHREADS) {
        int t = x / (50 * 28);
        int r = x - t * 50 * 28;
        int k = r / 28, j = r - k * 28;
        sm.w1T[t][k][j] = (j < 25) ? w1[t * 1250 + j * 50 + k] : 0.0f;
    }

    // ---- stage-2 roles: even/odd lane k-split over column pairs ----------
    // pairId -> (p, chunk c). Each thread of the pair covers 13 q-slots
    // (q = f32x2 index over k). half0: q 0..12; half1: q 12..24 with the
    // overlapping slot q=12 weight-zeroed -> uniform 13-iteration loops.
    const int pairId = tid >> 1;
    const int half   = tid & 1;
    const bool s2act = (pairId < 250);
    const int pp = s2act ? pairId : 249;  // clamp for safe addressing
    const int p  = pp % 50;
    const int c  = pp / 50;               // 0..4
    int t2, sbeg2, send2;
    if (c < 2) { t2 = 0; sbeg2 = c * 23;            send2 = sbeg2 + 23; }
    else       { t2 = 1; sbeg2 = 46 + (c - 2) * 31; send2 = sbeg2 + 31;
                 if (send2 > NNEI) send2 = NNEI; }
    const int qbase = half * 12;
    // shfl mask covering exactly this thread's even/odd pair. Both pair lanes
    // share pairId -> identical loop trip counts -> always converged at the
    // shfl. (Full-warp mask deadlocks: chunk boundaries split warps into
    // different trip counts.)
    const unsigned pmask = 0x3u << ((tid & 31) & ~1);

    ull wpA[13], wpB[13];
    {
        const float* wg = w2 + t2 * 5000;
        #pragma unroll
        for (int i = 0; i < 13; i++) {
            int q = qbase + i;
            bool z = (half == 1) && (i == 0);   // overlap slot zeroed
            float aLo = z ? 0.f : wg[(2 * q) * 100 + p];
            float aHi = z ? 0.f : wg[(2 * q + 1) * 100 + p];
            float bLo = z ? 0.f : wg[(2 * q) * 100 + p + 50];
            float bHi = z ? 0.f : wg[(2 * q + 1) * 100 + p + 50];
            wpA[i] = pack2(aLo, aHi);
            wpB[i] = pack2(bLo, bHi);
        }
    }
    const float b2A = b2[t2 * 100 + p];
    const float b2B = b2[t2 * 100 + p + 50];

    // ---- stage h1 roles: one k per thread, 9 neighbor segments -----------
    const bool h1act = (tid < 450);
    const int kh  = tid % 50;
    const int seg = tid / 50;             // 0..8
    int th1 = 0, hbeg = 0, hend = 0;
    if (h1act) {
        if (seg < 3) { th1 = 0; hbeg = (seg * 46) / 3;            hend = ((seg + 1) * 46) / 3; }
        else         { th1 = 1; hbeg = 46 + ((seg - 3) * 92) / 6; hend = 46 + ((seg - 2) * 92) / 6; }
    }
    const float b1k = h1act ? b1[th1 * 50 + kh] : 0.f;
    const int km = (kh < 25) ? kh : kh - 25;

    __syncthreads();

    // =====================  persistent row loop  ==========================
    for (int row = blockIdx.x; row < NROW; row += GRID) {
        const int f  = row >> 12;
        const int li = row & (NLOC - 1);

        // ---- stage 1: env matrix ----------------------------------------
        const long long ci = (long long)f * NALL + li;
        if (tid < NNEI) {
            const int s0 = tid;
            const float cx = coord[ci * 3 + 0];
            const float cy = coord[ci * 3 + 1];
            const float cz = coord[ci * 3 + 2];
            const int at = (int)load_idx(atype_, ci, is64a);
            long long nb = load_idx(nlist_, (long long)row * NNEI + s0, is64n);
            bool valid = (nb >= 0);
            long long j = valid ? nb : 0;
            const float* cp = coord + ((long long)f * NALL + j) * 3;
            float dx = cp[0] - cx, dy = cp[1] - cy, dz = cp[2] - cz;
            float r = sqrtf(dx * dx + dy * dy + dz * dz);
            float uu = (r - 0.5f) * (1.0f / 5.5f);
            float vv = uu * uu * uu * (uu * (-6.0f * uu + 15.0f) - 10.0f) + 1.0f;
            float w = (r < 0.5f) ? 1.0f : ((r >= 6.0f) ? 0.0f : vv);
            if (!valid) w = 0.0f;
            float inv = 1.0f / (r + 0.01f);
            float a0 = inv * w;
            float aw = inv * inv * w;
            int base = (at * NNEI + s0) * 4;
            sm.env[s0][0] = (a0      - mean[base + 0]) / stdv[base + 0];
            sm.env[s0][1] = (dx * aw - mean[base + 1]) / stdv[base + 1];
            sm.env[s0][2] = (dy * aw - mean[base + 2]) / stdv[base + 2];
            sm.env[s0][3] = (dz * aw - mean[base + 3]) / stdv[base + 3];
        }
        __syncthreads();

        // ---- stage h0: 138 x 25 (+ zero pads to 28) ---------------------
        for (int x = tid; x < NNEI * 28; x += NTHREADS) {
            int s0 = x / 28, j = x - s0 * 28;
            int t = (s0 >= SEC1);
            sm.h0[s0][j] = (j < 25)
                ? tanh_ap(sm.env[s0][0] * sm.w0s[t][j] + sm.b0s[t][j])
                : 0.0f;
        }
        __syncthreads();

        // ---- stage h1: one k per thread, weights in registers -----------
        if (h1act) {
            ulonglong2 wk[7];
            const ulonglong2* w1p = (const ulonglong2*)&sm.w1T[th1][kh][0];
            #pragma unroll
            for (int v = 0; v < 7; v++) wk[v] = w1p[v];
            for (int s0 = hbeg; s0 < hend; s0++) {
                const ulonglong2* h0p = (const ulonglong2*)&sm.h0[s0][0];
                ull a0 = 0ull, a1 = 0ull;
                #pragma unroll
                for (int v = 0; v < 7; v++) {
                    ulonglong2 h = h0p[v];
                    a0 = ffma2(h.x, wk[v].x, a0);
                    a1 = ffma2(h.y, wk[v].y, a1);
                }
                float acc = hsum2(fadd2(a0, a1)) + b1k;
                sm.h1[s0][kh] = tanh_ap(acc) + sm.h0[s0][km];
            }
        }
        __syncthreads();

        // ---- stage 2: k-split dot + pair-shfl merge; xyz += env^T g -----
        {
            float x0 = 0.f, x1 = 0.f, x2 = 0.f, x3 = 0.f;
            for (int s0 = sbeg2; s0 < send2; s0++) {
                const ull* hp = (const ull*)&sm.h1[s0][0];
                ull aA0 = 0ull, aA1 = 0ull, aB0 = 0ull, aB1 = 0ull;
                #pragma unroll
                for (int i = 0; i < 13; i += 2) {
                    ull h = hp[qbase + i];
                    aA0 = ffma2(h, wpA[i], aA0);
                    aB0 = ffma2(h, wpB[i], aB0);
                }
                #pragma unroll
                for (int i = 1; i < 13; i += 2) {
                    ull h = hp[qbase + i];
                    aA1 = ffma2(h, wpA[i], aA1);
                    aB1 = ffma2(h, wpB[i], aB1);
                }
                float accA = hsum2(fadd2(aA0, aA1));
                float accB = hsum2(fadd2(aB0, aB1));
                accA += __shfl_xor_sync(pmask, accA, 1);
                accB += __shfl_xor_sync(pmask, accB, 1);
                float myacc = half ? (accB + b2B) : (accA + b2A);
                float g = tanh_ap(myacc) + sm.h1[s0][p];
                float4 e = *(const float4*)sm.env[s0];
                x0 += e.x * g;
                x1 += e.y * g;
                x2 += e.z * g;
                x3 += e.w * g;
            }
            if (s2act) {
                const int col = half ? (p + 50) : p;
                sm.xyzp[c][0][col] = x0;
                sm.xyzp[c][1][col] = x1;
                sm.xyzp[c][2][col] = x2;
                sm.xyzp[c][3][col] = x3;
            }
        }
        __syncthreads();

        // ---- combine partials -------------------------------------------
        if (tid < MDIM) {
            const float sc = 1.0f / (float)NNEI;
            float x0 = 0.f, x1 = 0.f, x2 = 0.f, x3 = 0.f;
            #pragma unroll
            for (int cc = 0; cc < 5; cc++) {
                x0 += sm.xyzp[cc][0][tid];
                x1 += sm.xyzp[cc][1][tid];
                x2 += sm.xyzp[cc][2][tid];
                x3 += sm.xyzp[cc][3][tid];
            }
            sm.xyz[0][tid] = x0 * sc;
            sm.xyz[1][tid] = x1 * sc;
            sm.xyz[2][tid] = x2 * sc;
            sm.xyz[3][tid] = x3 * sc;
        }
        __syncthreads();

        // ---- epilogue Gram product: 400 threads, one float4 each --------
        if (tid < 400) {
            const int m  = tid % 100;
            const int a4 = (tid / 100) * 4;
            float y0 = sm.xyz[0][m], y1 = sm.xyz[1][m];
            float y2 = sm.xyz[2][m], y3 = sm.xyz[3][m];
            float4 v;
            v.x = y0 * sm.xyz[0][a4 + 0] + y1 * sm.xyz[1][a4 + 0]
                + y2 * sm.xyz[2][a4 + 0] + y3 * sm.xyz[3][a4 + 0];
            v.y = y0 * sm.xyz[0][a4 + 1] + y1 * sm.xyz[1][a4 + 1]
                + y2 * sm.xyz[2][a4 + 1] + y3 * sm.xyz[3][a4 + 1];
            v.z = y0 * sm.xyz[0][a4 + 2] + y1 * sm.xyz[1][a4 + 2]
                + y2 * sm.xyz[2][a4 + 2] + y3 * sm.xyz[3][a4 + 2];
            v.w = y0 * sm.xyz[0][a4 + 3] + y1 * sm.xyz[1][a4 + 3]
                + y2 * sm.xyz[2][a4 + 3] + y3 * sm.xyz[3][a4 + 3];
            *(float4*)(out + (long long)row * (MDIM * AXIS) + m * AXIS + a4) = v;
        }
        __syncthreads();
    }
}

extern "C" void kernel_launch(void* const* d_in, const int* in_sizes, int n_in,
                              void* d_out, int out_size)
{
    const void*  nlist = d_in[0];
    const float* coord = (const float*)d_in[1];
    const void*  atype = d_in[2];
    const float* mean  = (const float*)d_in[3];
    const float* stdv  = (const float*)d_in[4];
    const float* w0    = (const float*)d_in[5];
    const float* b0    = (const float*)d_in[6];
    const float* w1    = (const float*)d_in[7];
    const float* b1    = (const float*)d_in[8];
    const float* w2    = (const float*)d_in[9];
    const float* b2    = (const float*)d_in[10];
    float* out = (float*)d_out;

    cudaFuncSetAttribute(desc_kernel,
                         cudaFuncAttributeMaxDynamicSharedMemorySize,
                         (int)sizeof(SM));

    probe_kernel<<<1, 32>>>((const unsigned*)nlist, (const unsigned*)atype);
    desc_kernel<<<GRID, NTHREADS, sizeof(SM)>>>(
        nlist, coord, atype, mean, stdv, w0, b0, w1, b1, w2, b2, out);
}